// round 11
// baseline (speedup 1.0000x reference)
#include <cuda_runtime.h>
#include <cuda_fp16.h>
#include <mma.h>
#include <cstdint>

using namespace nvcuda;

#define N_NODES 50000
#define N_EDGES 800000

// ---------------- scratch (device globals; no allocation allowed) ----------
__device__ int    g_is64;
__device__ int    g_cnt[N_NODES];
__device__ int    g_fill[N_NODES];
__device__ int    g_rowptr[N_NODES + 1];
__device__ int2   g_cw[N_EDGES];               // (src, weight-bits)
__device__ float  g_dinv[N_NODES];
__device__ float  g_Af[(size_t)N_NODES * 128]; // fp32: A1, later H3
__device__ __half g_Hh[(size_t)N_NODES * 128]; // fp16: H1, later H2
__device__ __half g_Bh[(size_t)N_NODES * 64];  // fp16: A2

// ---------------- edge-index dtype sniffing --------------------------------
__device__ __forceinline__ int load_idx(const void* ei, long long pos) {
    if (g_is64) return (int)((const long long*)ei)[pos];
    return ((const int*)ei)[pos];
}

// ---------------- preprocessing ---------------------------------------------
__global__ void k_zero(const void* ei) {
    int i = blockIdx.x * blockDim.x + threadIdx.x;
    if (i < N_NODES) g_cnt[i] = 0;
    if (i == 0) {
        const unsigned long long* p = (const unsigned long long*)ei;
        int ok = 1;
        for (int k = 0; k < 16; k++)
            if (p[k] >= (unsigned long long)N_NODES) ok = 0;
        g_is64 = ok;
    }
}

__global__ void k_hist(const void* ei) {
    int e = blockIdx.x * blockDim.x + threadIdx.x;
    if (e < N_EDGES) {
        int d = load_idx(ei, (long long)N_EDGES + e);
        atomicAdd(&g_cnt[d], 1);
    }
}

__global__ void k_scan() {
    __shared__ int wsum[32];
    __shared__ int s_carry;
    int t = threadIdx.x, lane = t & 31, wid = t >> 5;
    if (t == 0) s_carry = 0;
    __syncthreads();
    for (int base = 0; base < N_NODES; base += 1024) {
        int i = base + t;
        int c = (i < N_NODES) ? g_cnt[i] : 0;
        int v = c;
#pragma unroll
        for (int off = 1; off < 32; off <<= 1) {
            int u = __shfl_up_sync(0xffffffffu, v, off);
            if (lane >= off) v += u;
        }
        if (lane == 31) wsum[wid] = v;
        __syncthreads();
        if (wid == 0) {
            int w = wsum[lane];
#pragma unroll
            for (int off = 1; off < 32; off <<= 1) {
                int u = __shfl_up_sync(0xffffffffu, w, off);
                if (lane >= off) w += u;
            }
            wsum[lane] = w;
        }
        __syncthreads();
        int woff = (wid > 0) ? wsum[wid - 1] : 0;
        int carry = s_carry;
        int incl = v + woff + carry;
        int excl = incl - c;
        if (i < N_NODES) {
            g_rowptr[i] = excl;
            g_fill[i]   = excl;
            g_dinv[i]   = rsqrtf((float)(c + 1));   // +1 self loop
        }
        __syncthreads();
        if (t == 1023) s_carry = incl;
        __syncthreads();
    }
    if (t == 0) g_rowptr[N_NODES] = s_carry;
}

__global__ void k_fill(const void* ei) {
    int e = blockIdx.x * blockDim.x + threadIdx.x;
    if (e < N_EDGES) {
        int s = load_idx(ei, e);
        int d = load_idx(ei, (long long)N_EDGES + e);
        int pos = atomicAdd(&g_fill[d], 1);
        float w = g_dinv[s] * g_dinv[d];
        g_cw[pos] = make_int2(s, __float_as_int(w));
    }
}

// ---------------- wmma GEMM: Y[128 rows/CTA, NO] = X @ W (+bias) -----------
template <int K, int NO, bool BIAS, bool OUTH>
__global__ void __launch_bounds__(256) k_wgemm(const float* __restrict__ X,
                                               const float* __restrict__ W,
                                               const float* __restrict__ bias,
                                               void* __restrict__ Yout) {
    constexpr int AS = K + 8;
    constexpr int BS = NO + 8;
    constexpr int WCOL = NO / 2;
    constexpr int NFRAG = WCOL / 16;
    extern __shared__ __half sm[];
    __half* Ash = sm;                       // [128][AS]
    __half* Bsh = sm + 128 * AS;            // [K][BS]
    float* biasTile = (float*)(sm + 128 * AS + (size_t)K * BS); // [16][NO]

    int tid = threadIdx.x, wid = tid >> 5;
    int warp_m = wid & 3, warp_n = wid >> 2;
    int r0 = blockIdx.x * 128;

#pragma unroll 4
    for (int i = tid; i < 128 * (K / 4); i += 256) {
        int row = i / (K / 4), c4 = i % (K / 4);
        int grow = r0 + row;
        if (grow >= N_NODES) grow = 0;
        float4 v = __ldg(((const float4*)(X + (size_t)grow * K)) + c4);
        __half2* dst = (__half2*)(Ash + row * AS + c4 * 4);
        dst[0] = __floats2half2_rn(v.x, v.y);
        dst[1] = __floats2half2_rn(v.z, v.w);
    }
#pragma unroll 4
    for (int i = tid; i < K * (NO / 4); i += 256) {
        int row = i / (NO / 4), c4 = i % (NO / 4);
        float4 v = __ldg(((const float4*)(W + (size_t)row * NO)) + c4);
        __half2* dst = (__half2*)(Bsh + row * BS + c4 * 4);
        dst[0] = __floats2half2_rn(v.x, v.y);
        dst[1] = __floats2half2_rn(v.z, v.w);
    }
    if (BIAS) {
        for (int i = tid; i < 16 * NO; i += 256)
            biasTile[i] = bias[i % NO];
    }
    __syncthreads();

    wmma::fragment<wmma::accumulator, 16, 16, 16, float> acc[2][NFRAG];
#pragma unroll
    for (int i = 0; i < 2; i++)
#pragma unroll
        for (int j = 0; j < NFRAG; j++) {
            if (BIAS)
                wmma::load_matrix_sync(acc[i][j],
                                       biasTile + warp_n * WCOL + j * 16,
                                       NO, wmma::mem_row_major);
            else
                wmma::fill_fragment(acc[i][j], 0.0f);
        }

#pragma unroll
    for (int kk = 0; kk < K; kk += 16) {
        wmma::fragment<wmma::matrix_a, 16, 16, 16, __half, wmma::row_major> a0, a1;
        wmma::load_matrix_sync(a0, Ash + (warp_m * 32 + 0) * AS + kk, AS);
        wmma::load_matrix_sync(a1, Ash + (warp_m * 32 + 16) * AS + kk, AS);
#pragma unroll
        for (int j = 0; j < NFRAG; j++) {
            wmma::fragment<wmma::matrix_b, 16, 16, 16, __half, wmma::row_major> b;
            wmma::load_matrix_sync(b, Bsh + kk * BS + warp_n * WCOL + j * 16, BS);
            wmma::mma_sync(acc[0][j], a0, b, acc[0][j]);
            wmma::mma_sync(acc[1][j], a1, b, acc[1][j]);
        }
    }

    if constexpr (OUTH) {
        __syncthreads();
        float* Fsh = (float*)sm;            // [128][NO] fp32 staging
#pragma unroll
        for (int i = 0; i < 2; i++) {
            int lrow = warp_m * 32 + i * 16;
#pragma unroll
            for (int j = 0; j < NFRAG; j++)
                wmma::store_matrix_sync(Fsh + (size_t)lrow * NO + warp_n * WCOL + j * 16,
                                        acc[i][j], NO, wmma::mem_row_major);
        }
        __syncthreads();
        __half* Yh = (__half*)Yout;
#pragma unroll 4
        for (int i = tid; i < 128 * (NO / 4); i += 256) {
            int row = i / (NO / 4), c4 = i % (NO / 4);
            int grow = r0 + row;
            if (grow < N_NODES) {
                float4 v = *(const float4*)(Fsh + (size_t)row * NO + c4 * 4);
                uint2 o;
                __half2 h0 = __floats2half2_rn(v.x, v.y);
                __half2 h1 = __floats2half2_rn(v.z, v.w);
                o.x = *(uint32_t*)&h0;
                o.y = *(uint32_t*)&h1;
                *(uint2*)(Yh + (size_t)grow * NO + c4 * 4) = o;
            }
        }
    } else {
        float* Y = (float*)Yout;
#pragma unroll
        for (int i = 0; i < 2; i++) {
            int grow = r0 + warp_m * 32 + i * 16;
            if (grow < N_NODES) {
#pragma unroll
                for (int j = 0; j < NFRAG; j++)
                    wmma::store_matrix_sync(Y + (size_t)grow * NO + warp_n * WCOL + j * 16,
                                            acc[i][j], NO, wmma::mem_row_major);
            }
        }
    }
}

// ---------------- sparse aggregation: one warp per node --------------------
// Full-MLP tail: every batch is 8 gathers in flight; out-of-range lanes are
// clamped to a valid index (e-1) with weight forced to 0.
template <int F, bool RELU, bool BIAS, bool OUTH>
__global__ void k_agg(const __half* __restrict__ H, const float* __restrict__ b,
                      void* __restrict__ outp) {
    int gw   = (blockIdx.x * blockDim.x + threadIdx.x) >> 5;
    int lane = threadIdx.x & 31;
    if (gw >= N_NODES) return;
    int s = g_rowptr[gw], e = g_rowptr[gw + 1];

    if constexpr (F == 128) {
        float4 a0 = make_float4(0.f, 0.f, 0.f, 0.f);
        float4 a1 = make_float4(0.f, 0.f, 0.f, 0.f);
        if (e > s) {
            for (int j = s; j < e; j += 8) {
                int2 cw[8];
                uint2 v[8];
#pragma unroll
                for (int q = 0; q < 8; q++) {
                    int idx = j + q;
                    int2 c = __ldg(&g_cw[idx < e ? idx : e - 1]);
                    if (idx >= e) c.y = 0;        // weight = 0.0f
                    cw[q] = c;
                }
#pragma unroll
                for (int q = 0; q < 8; q++)
                    v[q] = __ldg(((const uint2*)(H + (size_t)cw[q].x * 128)) + lane);
#pragma unroll
                for (int q = 0; q < 8; q++) {
                    float w = __int_as_float(cw[q].y);
                    float2 f0 = __half22float2(*(__half2*)&v[q].x);
                    float2 f1 = __half22float2(*(__half2*)&v[q].y);
                    float4& a = (q & 1) ? a1 : a0;
                    a.x = fmaf(w, f0.x, a.x); a.y = fmaf(w, f0.y, a.y);
                    a.z = fmaf(w, f1.x, a.z); a.w = fmaf(w, f1.y, a.w);
                }
            }
        }
        float di = g_dinv[gw];
        float wl = di * di;
        uint2 vs = ((const uint2*)(H + (size_t)gw * 128))[lane];
        float2 s0 = __half22float2(*(__half2*)&vs.x);
        float2 s1 = __half22float2(*(__half2*)&vs.y);
        a0.x = fmaf(wl, s0.x, a0.x); a0.y = fmaf(wl, s0.y, a0.y);
        a0.z = fmaf(wl, s1.x, a0.z); a0.w = fmaf(wl, s1.y, a0.w);
        a0.x += a1.x; a0.y += a1.y; a0.z += a1.z; a0.w += a1.w;
        if (BIAS) {
            float4 bb = ((const float4*)b)[lane];
            a0.x += bb.x; a0.y += bb.y; a0.z += bb.z; a0.w += bb.w;
        }
        if (RELU) {
            a0.x = fmaxf(a0.x, 0.f); a0.y = fmaxf(a0.y, 0.f);
            a0.z = fmaxf(a0.z, 0.f); a0.w = fmaxf(a0.w, 0.f);
        }
        if constexpr (OUTH) {
            uint2 o;
            *(__half2*)&o.x = __floats2half2_rn(a0.x, a0.y);
            *(__half2*)&o.y = __floats2half2_rn(a0.z, a0.w);
            ((uint2*)((__half*)outp + (size_t)gw * 128))[lane] = o;
        } else {
            ((float4*)((float*)outp + (size_t)gw * 128))[lane] = a0;
        }
    } else { // F == 64
        float2 a0 = make_float2(0.f, 0.f);
        float2 a1 = make_float2(0.f, 0.f);
        if (e > s) {
            for (int j = s; j < e; j += 8) {
                int2 cw[8];
                unsigned v[8];
#pragma unroll
                for (int q = 0; q < 8; q++) {
                    int idx = j + q;
                    int2 c = __ldg(&g_cw[idx < e ? idx : e - 1]);
                    if (idx >= e) c.y = 0;
                    cw[q] = c;
                }
#pragma unroll
                for (int q = 0; q < 8; q++)
                    v[q] = __ldg(((const unsigned*)(H + (size_t)cw[q].x * 64)) + lane);
#pragma unroll
                for (int q = 0; q < 8; q++) {
                    float w = __int_as_float(cw[q].y);
                    float2 f = __half22float2(*(__half2*)&v[q]);
                    float2& a = (q & 1) ? a1 : a0;
                    a.x = fmaf(w, f.x, a.x); a.y = fmaf(w, f.y, a.y);
                }
            }
        }
        float di = g_dinv[gw];
        float wl = di * di;
        unsigned vs = ((const unsigned*)(H + (size_t)gw * 64))[lane];
        float2 sf = __half22float2(*(__half2*)&vs);
        a0.x = fmaf(wl, sf.x, a0.x); a0.y = fmaf(wl, sf.y, a0.y);
        a0.x += a1.x; a0.y += a1.y;
        if (BIAS) {
            float2 bb = ((const float2*)b)[lane];
            a0.x += bb.x; a0.y += bb.y;
        }
        if (RELU) { a0.x = fmaxf(a0.x, 0.f); a0.y = fmaxf(a0.y, 0.f); }
        if constexpr (OUTH) {
            unsigned o;
            *(__half2*)&o = __floats2half2_rn(a0.x, a0.y);
            ((unsigned*)((__half*)outp + (size_t)gw * 64))[lane] = o;
        } else {
            ((float2*)((float*)outp + (size_t)gw * 64))[lane] = a0;
        }
    }
}

// ---------------- launch ----------------------------------------------------
extern "C" void kernel_launch(void* const* d_in, const int* in_sizes, int n_in,
                              void* d_out, int out_size) {
    const float* x  = (const float*)d_in[0];
    const void*  ei = d_in[1];
    const float* W1 = (const float*)d_in[2];
    const float* b1 = (const float*)d_in[3];
    const float* W2 = (const float*)d_in[4];
    const float* b2 = (const float*)d_in[5];
    const float* W3 = (const float*)d_in[6];
    const float* b3 = (const float*)d_in[7];
    float* out = (float*)d_out;

    void *pAf = nullptr, *pHh = nullptr, *pBh = nullptr;
    cudaGetSymbolAddress(&pAf, g_Af);
    cudaGetSymbolAddress(&pHh, g_Hh);
    cudaGetSymbolAddress(&pBh, g_Bh);
    float*  Af = (float*)pAf;
    __half* Hh = (__half*)pHh;
    __half* Bh = (__half*)pBh;

    constexpr int SM1a = (128 * 136 + 128 * 136) * 2;
    constexpr int SM1b = 128 * 128 * 4;
    constexpr int SM1 = SM1a > SM1b ? SM1a : SM1b;                 // 69632
    constexpr int SM2a = (128 * 136 + 128 * 72) * 2;
    constexpr int SM2b = 128 * 64 * 4;
    constexpr int SM2 = SM2a > SM2b ? SM2a : SM2b;                 // 53248
    constexpr int SM3 = (128 * 72 + 64 * 136) * 2 + 16 * 128 * 4;  // 44032
    cudaFuncSetAttribute(k_wgemm<128, 128, false, true>,
                         cudaFuncAttributeMaxDynamicSharedMemorySize, SM1);
    cudaFuncSetAttribute(k_wgemm<128, 64, false, true>,
                         cudaFuncAttributeMaxDynamicSharedMemorySize, SM2);
    cudaFuncSetAttribute(k_wgemm<64, 128, true, false>,
                         cudaFuncAttributeMaxDynamicSharedMemorySize, SM3);

    const int TB = 256;
    int gN = (N_NODES + TB - 1) / TB;
    int gE = (N_EDGES + TB - 1) / TB;
    int aggBlocks = (N_NODES * 32 + TB - 1) / TB;
    int gT = (N_NODES + 127) / 128;

    // Fork wgemm1 (depends only on x, W1) onto a side stream so it overlaps
    // with CSR preprocessing. Created per call (host-side only; ~3 calls).
    cudaStream_t s2;
    cudaEvent_t ev0, ev1;
    cudaStreamCreateWithFlags(&s2, cudaStreamNonBlocking);
    cudaEventCreateWithFlags(&ev0, cudaEventDisableTiming);
    cudaEventCreateWithFlags(&ev1, cudaEventDisableTiming);

    cudaEventRecord(ev0, 0);
    cudaStreamWaitEvent(s2, ev0, 0);
    k_wgemm<128, 128, false, true><<<gT, 256, SM1, s2>>>(x, W1, nullptr, Hh); // H1
    cudaEventRecord(ev1, s2);

    // preprocessing on the main stream (concurrent with wgemm1)
    k_zero<<<gN, TB>>>(ei);
    k_hist<<<gE, TB>>>(ei);
    k_scan<<<1, 1024>>>();
    k_fill<<<gE, TB>>>(ei);

    cudaStreamWaitEvent(0, ev1, 0);   // join: agg1 needs H1 + CSR

    // layer 1: A1 = relu(agg(H1) + b1)  [fp32]
    k_agg<128, true, true, false><<<aggBlocks, TB>>>(Hh, b1, Af);
    // layer 2: H2 = A1 @ W2 [fp16]; A2 = relu(agg(H2) + b2) [fp16]
    k_wgemm<128, 64, false, true><<<gT, 256, SM2>>>(Af, W2, nullptr, Hh);
    k_agg<64, true, true, true><<<aggBlocks, TB>>>(Hh, b2, Bh);
    // layer 3: H3 = agg(A2) [fp32]; out = H3 @ W3 + b3
    k_agg<64, false, false, false><<<aggBlocks, TB>>>(Bh, nullptr, Af);
    k_wgemm<64, 128, true, false><<<gT, 256, SM3>>>(Af, W3, b3, out);
}

// round 12
// speedup vs baseline: 1.2322x; 1.2322x over previous
#include <cuda_runtime.h>
#include <cuda_fp16.h>
#include <mma.h>
#include <cstdint>

using namespace nvcuda;

#define N_NODES 50000
#define N_EDGES 800000
#define SCAN_BLOCKS 49

// ---------------- scratch (device globals; no allocation allowed) ----------
__device__ int    g_is64;
__device__ int    g_cnt[N_NODES];
__device__ int    g_fill[N_NODES];
__device__ int    g_rowptr[N_NODES + 1];
__device__ int    g_bsum[64];
__device__ int2   g_cw[N_EDGES];               // (src, weight-bits)
__device__ float  g_dinv[N_NODES];
__device__ float  g_Af[(size_t)N_NODES * 128]; // fp32: A1, later H3
__device__ __half g_Hh[(size_t)N_NODES * 128]; // fp16: H1, later H2
__device__ __half g_Bh[(size_t)N_NODES * 64];  // fp16: A2

// ---------------- edge-index dtype sniffing --------------------------------
__device__ __forceinline__ int load_idx(const void* ei, long long pos) {
    if (g_is64) return (int)((const long long*)ei)[pos];
    return ((const int*)ei)[pos];
}

// ---------------- preprocessing ---------------------------------------------
__global__ void k_zero(const void* ei) {
    int i = blockIdx.x * blockDim.x + threadIdx.x;
    if (i < N_NODES) g_cnt[i] = 0;
    if (i == 0) {
        const unsigned long long* p = (const unsigned long long*)ei;
        int ok = 1;
        for (int k = 0; k < 16; k++)
            if (p[k] >= (unsigned long long)N_NODES) ok = 0;
        g_is64 = ok;
    }
}

__global__ void k_hist(const void* ei) {
    int e = blockIdx.x * blockDim.x + threadIdx.x;
    if (e < N_EDGES) {
        int d = load_idx(ei, (long long)N_EDGES + e);
        atomicAdd(&g_cnt[d], 1);
    }
}

// pass 1: block-local exclusive scan of g_cnt (1024 elems/block)
__global__ void k_scan1() {
    __shared__ int wsum[32];
    int t = threadIdx.x, lane = t & 31, wid = t >> 5;
    int i = blockIdx.x * 1024 + t;
    int c = (i < N_NODES) ? g_cnt[i] : 0;
    int v = c;
#pragma unroll
    for (int off = 1; off < 32; off <<= 1) {
        int u = __shfl_up_sync(0xffffffffu, v, off);
        if (lane >= off) v += u;
    }
    if (lane == 31) wsum[wid] = v;
    __syncthreads();
    if (wid == 0) {
        int w = wsum[lane];
#pragma unroll
        for (int off = 1; off < 32; off <<= 1) {
            int u = __shfl_up_sync(0xffffffffu, w, off);
            if (lane >= off) w += u;
        }
        wsum[lane] = w;
    }
    __syncthreads();
    int woff = (wid > 0) ? wsum[wid - 1] : 0;
    int incl = v + woff;
    if (i < N_NODES) g_rowptr[i] = incl - c;   // block-local exclusive
    if (t == 1023) g_bsum[blockIdx.x] = incl;  // block total
}

// pass 2: exclusive scan of the 49 block sums (+ total into rowptr[N])
__global__ void k_scan2() {
    __shared__ int sh[64];
    int t = threadIdx.x;
    int v = (t < SCAN_BLOCKS) ? g_bsum[t] : 0;
    sh[t] = v;
    __syncthreads();
#pragma unroll
    for (int off = 1; off < 64; off <<= 1) {
        int u = (t >= off) ? sh[t - off] : 0;
        __syncthreads();
        sh[t] += u;
        __syncthreads();
    }
    if (t < SCAN_BLOCKS) g_bsum[t] = sh[t] - v;  // exclusive
    if (t == 63) g_rowptr[N_NODES] = sh[63];     // grand total
}

// pass 3: add block offsets; init fill cursor and dinv
__global__ void k_scan3() {
    int i = blockIdx.x * 1024 + threadIdx.x;
    if (i < N_NODES) {
        int r = g_rowptr[i] + g_bsum[blockIdx.x];
        g_rowptr[i] = r;
        g_fill[i]   = r;
        g_dinv[i]   = rsqrtf((float)(g_cnt[i] + 1));   // +1 self loop
    }
}

__global__ void k_fill(const void* ei) {
    int e = blockIdx.x * blockDim.x + threadIdx.x;
    if (e < N_EDGES) {
        int s = load_idx(ei, e);
        int d = load_idx(ei, (long long)N_EDGES + e);
        int pos = atomicAdd(&g_fill[d], 1);
        float w = g_dinv[s] * g_dinv[d];
        g_cw[pos] = make_int2(s, __float_as_int(w));
    }
}

// ---------------- wmma GEMM: Y[128 rows/CTA, NO] = X @ W (+bias) -----------
template <int K, int NO, bool BIAS, bool OUTH>
__global__ void __launch_bounds__(256) k_wgemm(const float* __restrict__ X,
                                               const float* __restrict__ W,
                                               const float* __restrict__ bias,
                                               void* __restrict__ Yout) {
    constexpr int AS = K + 8;
    constexpr int BS = NO + 8;
    constexpr int WCOL = NO / 2;
    constexpr int NFRAG = WCOL / 16;
    extern __shared__ __half sm[];
    __half* Ash = sm;                       // [128][AS]
    __half* Bsh = sm + 128 * AS;            // [K][BS]
    float* biasTile = (float*)(sm + 128 * AS + (size_t)K * BS); // [16][NO]

    int tid = threadIdx.x, wid = tid >> 5;
    int warp_m = wid & 3, warp_n = wid >> 2;
    int r0 = blockIdx.x * 128;

#pragma unroll 4
    for (int i = tid; i < 128 * (K / 4); i += 256) {
        int row = i / (K / 4), c4 = i % (K / 4);
        int grow = r0 + row;
        if (grow >= N_NODES) grow = 0;
        float4 v = __ldg(((const float4*)(X + (size_t)grow * K)) + c4);
        __half2* dst = (__half2*)(Ash + row * AS + c4 * 4);
        dst[0] = __floats2half2_rn(v.x, v.y);
        dst[1] = __floats2half2_rn(v.z, v.w);
    }
#pragma unroll 4
    for (int i = tid; i < K * (NO / 4); i += 256) {
        int row = i / (NO / 4), c4 = i % (NO / 4);
        float4 v = __ldg(((const float4*)(W + (size_t)row * NO)) + c4);
        __half2* dst = (__half2*)(Bsh + row * BS + c4 * 4);
        dst[0] = __floats2half2_rn(v.x, v.y);
        dst[1] = __floats2half2_rn(v.z, v.w);
    }
    if (BIAS) {
        for (int i = tid; i < 16 * NO; i += 256)
            biasTile[i] = bias[i % NO];
    }
    __syncthreads();

    wmma::fragment<wmma::accumulator, 16, 16, 16, float> acc[2][NFRAG];
#pragma unroll
    for (int i = 0; i < 2; i++)
#pragma unroll
        for (int j = 0; j < NFRAG; j++) {
            if (BIAS)
                wmma::load_matrix_sync(acc[i][j],
                                       biasTile + warp_n * WCOL + j * 16,
                                       NO, wmma::mem_row_major);
            else
                wmma::fill_fragment(acc[i][j], 0.0f);
        }

#pragma unroll
    for (int kk = 0; kk < K; kk += 16) {
        wmma::fragment<wmma::matrix_a, 16, 16, 16, __half, wmma::row_major> a0, a1;
        wmma::load_matrix_sync(a0, Ash + (warp_m * 32 + 0) * AS + kk, AS);
        wmma::load_matrix_sync(a1, Ash + (warp_m * 32 + 16) * AS + kk, AS);
#pragma unroll
        for (int j = 0; j < NFRAG; j++) {
            wmma::fragment<wmma::matrix_b, 16, 16, 16, __half, wmma::row_major> b;
            wmma::load_matrix_sync(b, Bsh + kk * BS + warp_n * WCOL + j * 16, BS);
            wmma::mma_sync(acc[0][j], a0, b, acc[0][j]);
            wmma::mma_sync(acc[1][j], a1, b, acc[1][j]);
        }
    }

    if constexpr (OUTH) {
        __syncthreads();
        float* Fsh = (float*)sm;            // [128][NO] fp32 staging
#pragma unroll
        for (int i = 0; i < 2; i++) {
            int lrow = warp_m * 32 + i * 16;
#pragma unroll
            for (int j = 0; j < NFRAG; j++)
                wmma::store_matrix_sync(Fsh + (size_t)lrow * NO + warp_n * WCOL + j * 16,
                                        acc[i][j], NO, wmma::mem_row_major);
        }
        __syncthreads();
        __half* Yh = (__half*)Yout;
#pragma unroll 4
        for (int i = tid; i < 128 * (NO / 4); i += 256) {
            int row = i / (NO / 4), c4 = i % (NO / 4);
            int grow = r0 + row;
            if (grow < N_NODES) {
                float4 v = *(const float4*)(Fsh + (size_t)row * NO + c4 * 4);
                uint2 o;
                __half2 h0 = __floats2half2_rn(v.x, v.y);
                __half2 h1 = __floats2half2_rn(v.z, v.w);
                o.x = *(uint32_t*)&h0;
                o.y = *(uint32_t*)&h1;
                *(uint2*)(Yh + (size_t)grow * NO + c4 * 4) = o;
            }
        }
    } else {
        float* Y = (float*)Yout;
#pragma unroll
        for (int i = 0; i < 2; i++) {
            int grow = r0 + warp_m * 32 + i * 16;
            if (grow < N_NODES) {
#pragma unroll
                for (int j = 0; j < NFRAG; j++)
                    wmma::store_matrix_sync(Y + (size_t)grow * NO + warp_n * WCOL + j * 16,
                                            acc[i][j], NO, wmma::mem_row_major);
            }
        }
    }
}

// ---------------- sparse aggregation: one warp per node --------------------
template <int F, bool RELU, bool BIAS, bool OUTH>
__global__ void k_agg(const __half* __restrict__ H, const float* __restrict__ b,
                      void* __restrict__ outp) {
    int gw   = (blockIdx.x * blockDim.x + threadIdx.x) >> 5;
    int lane = threadIdx.x & 31;
    if (gw >= N_NODES) return;
    int s = g_rowptr[gw], e = g_rowptr[gw + 1];

    if constexpr (F == 128) {
        float4 a0 = make_float4(0.f, 0.f, 0.f, 0.f);
        float4 a1 = make_float4(0.f, 0.f, 0.f, 0.f);
        if (e > s) {
            for (int j = s; j < e; j += 8) {
                int2 cw[8];
                uint2 v[8];
#pragma unroll
                for (int q = 0; q < 8; q++) {
                    int idx = j + q;
                    int2 c = __ldg(&g_cw[idx < e ? idx : e - 1]);
                    if (idx >= e) c.y = 0;        // weight = 0.0f
                    cw[q] = c;
                }
#pragma unroll
                for (int q = 0; q < 8; q++)
                    v[q] = __ldg(((const uint2*)(H + (size_t)cw[q].x * 128)) + lane);
#pragma unroll
                for (int q = 0; q < 8; q++) {
                    float w = __int_as_float(cw[q].y);
                    float2 f0 = __half22float2(*(__half2*)&v[q].x);
                    float2 f1 = __half22float2(*(__half2*)&v[q].y);
                    float4& a = (q & 1) ? a1 : a0;
                    a.x = fmaf(w, f0.x, a.x); a.y = fmaf(w, f0.y, a.y);
                    a.z = fmaf(w, f1.x, a.z); a.w = fmaf(w, f1.y, a.w);
                }
            }
        }
        float di = g_dinv[gw];
        float wl = di * di;
        uint2 vs = ((const uint2*)(H + (size_t)gw * 128))[lane];
        float2 s0 = __half22float2(*(__half2*)&vs.x);
        float2 s1 = __half22float2(*(__half2*)&vs.y);
        a0.x = fmaf(wl, s0.x, a0.x); a0.y = fmaf(wl, s0.y, a0.y);
        a0.z = fmaf(wl, s1.x, a0.z); a0.w = fmaf(wl, s1.y, a0.w);
        a0.x += a1.x; a0.y += a1.y; a0.z += a1.z; a0.w += a1.w;
        if (BIAS) {
            float4 bb = ((const float4*)b)[lane];
            a0.x += bb.x; a0.y += bb.y; a0.z += bb.z; a0.w += bb.w;
        }
        if (RELU) {
            a0.x = fmaxf(a0.x, 0.f); a0.y = fmaxf(a0.y, 0.f);
            a0.z = fmaxf(a0.z, 0.f); a0.w = fmaxf(a0.w, 0.f);
        }
        if constexpr (OUTH) {
            uint2 o;
            *(__half2*)&o.x = __floats2half2_rn(a0.x, a0.y);
            *(__half2*)&o.y = __floats2half2_rn(a0.z, a0.w);
            ((uint2*)((__half*)outp + (size_t)gw * 128))[lane] = o;
        } else {
            ((float4*)((float*)outp + (size_t)gw * 128))[lane] = a0;
        }
    } else { // F == 64
        float2 a0 = make_float2(0.f, 0.f);
        float2 a1 = make_float2(0.f, 0.f);
        if (e > s) {
            for (int j = s; j < e; j += 8) {
                int2 cw[8];
                unsigned v[8];
#pragma unroll
                for (int q = 0; q < 8; q++) {
                    int idx = j + q;
                    int2 c = __ldg(&g_cw[idx < e ? idx : e - 1]);
                    if (idx >= e) c.y = 0;
                    cw[q] = c;
                }
#pragma unroll
                for (int q = 0; q < 8; q++)
                    v[q] = __ldg(((const unsigned*)(H + (size_t)cw[q].x * 64)) + lane);
#pragma unroll
                for (int q = 0; q < 8; q++) {
                    float w = __int_as_float(cw[q].y);
                    float2 f = __half22float2(*(__half2*)&v[q]);
                    float2& a = (q & 1) ? a1 : a0;
                    a.x = fmaf(w, f.x, a.x); a.y = fmaf(w, f.y, a.y);
                }
            }
        }
        float di = g_dinv[gw];
        float wl = di * di;
        unsigned vs = ((const unsigned*)(H + (size_t)gw * 64))[lane];
        float2 sf = __half22float2(*(__half2*)&vs);
        a0.x = fmaf(wl, sf.x, a0.x); a0.y = fmaf(wl, sf.y, a0.y);
        a0.x += a1.x; a0.y += a1.y;
        if (BIAS) {
            float2 bb = ((const float2*)b)[lane];
            a0.x += bb.x; a0.y += bb.y;
        }
        if (RELU) { a0.x = fmaxf(a0.x, 0.f); a0.y = fmaxf(a0.y, 0.f); }
        if constexpr (OUTH) {
            unsigned o;
            *(__half2*)&o = __floats2half2_rn(a0.x, a0.y);
            ((unsigned*)((__half*)outp + (size_t)gw * 64))[lane] = o;
        } else {
            ((float2*)((float*)outp + (size_t)gw * 64))[lane] = a0;
        }
    }
}

// ---------------- launch ----------------------------------------------------
extern "C" void kernel_launch(void* const* d_in, const int* in_sizes, int n_in,
                              void* d_out, int out_size) {
    const float* x  = (const float*)d_in[0];
    const void*  ei = d_in[1];
    const float* W1 = (const float*)d_in[2];
    const float* b1 = (const float*)d_in[3];
    const float* W2 = (const float*)d_in[4];
    const float* b2 = (const float*)d_in[5];
    const float* W3 = (const float*)d_in[6];
    const float* b3 = (const float*)d_in[7];
    float* out = (float*)d_out;

    void *pAf = nullptr, *pHh = nullptr, *pBh = nullptr;
    cudaGetSymbolAddress(&pAf, g_Af);
    cudaGetSymbolAddress(&pHh, g_Hh);
    cudaGetSymbolAddress(&pBh, g_Bh);
    float*  Af = (float*)pAf;
    __half* Hh = (__half*)pHh;
    __half* Bh = (__half*)pBh;

    constexpr int SM1a = (128 * 136 + 128 * 136) * 2;
    constexpr int SM1b = 128 * 128 * 4;
    constexpr int SM1 = SM1a > SM1b ? SM1a : SM1b;                 // 69632
    constexpr int SM2a = (128 * 136 + 128 * 72) * 2;
    constexpr int SM2b = 128 * 64 * 4;
    constexpr int SM2 = SM2a > SM2b ? SM2a : SM2b;                 // 53248
    constexpr int SM3 = (128 * 72 + 64 * 136) * 2 + 16 * 128 * 4;  // 44032
    cudaFuncSetAttribute(k_wgemm<128, 128, false, true>,
                         cudaFuncAttributeMaxDynamicSharedMemorySize, SM1);
    cudaFuncSetAttribute(k_wgemm<128, 64, false, true>,
                         cudaFuncAttributeMaxDynamicSharedMemorySize, SM2);
    cudaFuncSetAttribute(k_wgemm<64, 128, true, false>,
                         cudaFuncAttributeMaxDynamicSharedMemorySize, SM3);

    const int TB = 256;
    int gN = (N_NODES + TB - 1) / TB;
    int gE = (N_EDGES + TB - 1) / TB;
    int aggBlocks = (N_NODES * 32 + TB - 1) / TB;
    int gT = (N_NODES + 127) / 128;

    // Fork wgemm1 (depends only on x, W1) onto a side stream so it overlaps
    // with CSR preprocessing. Created per call (host-side only; ~3 calls).
    cudaStream_t s2;
    cudaEvent_t ev0, ev1;
    cudaStreamCreateWithFlags(&s2, cudaStreamNonBlocking);
    cudaEventCreateWithFlags(&ev0, cudaEventDisableTiming);
    cudaEventCreateWithFlags(&ev1, cudaEventDisableTiming);

    cudaEventRecord(ev0, 0);
    cudaStreamWaitEvent(s2, ev0, 0);
    k_wgemm<128, 128, false, true><<<gT, 256, SM1, s2>>>(x, W1, nullptr, Hh); // H1
    cudaEventRecord(ev1, s2);

    // preprocessing on the main stream (concurrent with wgemm1)
    k_zero<<<gN, TB>>>(ei);
    k_hist<<<gE, TB>>>(ei);
    k_scan1<<<SCAN_BLOCKS, 1024>>>();
    k_scan2<<<1, 64>>>();
    k_scan3<<<SCAN_BLOCKS, 1024>>>();
    k_fill<<<gE, TB>>>(ei);

    cudaStreamWaitEvent(0, ev1, 0);   // join: agg1 needs H1 + CSR

    // layer 1: A1 = relu(agg(H1) + b1)  [fp32]
    k_agg<128, true, true, false><<<aggBlocks, TB>>>(Hh, b1, Af);
    // layer 2: H2 = A1 @ W2 [fp16]; A2 = relu(agg(H2) + b2) [fp16]
    k_wgemm<128, 64, false, true><<<gT, 256, SM2>>>(Af, W2, nullptr, Hh);
    k_agg<64, true, true, true><<<aggBlocks, TB>>>(Hh, b2, Bh);
    // layer 3: H3 = agg(A2) [fp32]; out = H3 @ W3 + b3
    k_agg<64, false, false, false><<<aggBlocks, TB>>>(Bh, nullptr, Af);
    k_wgemm<64, 128, true, false><<<gT, 256, SM3>>>(Af, W3, b3, out);
}

// round 13
// speedup vs baseline: 1.2421x; 1.0080x over previous
#include <cuda_runtime.h>
#include <cuda_fp16.h>
#include <mma.h>
#include <cstdint>

using namespace nvcuda;

#define N_NODES 50000
#define N_EDGES 800000
#define SCAN_BLOCKS 49

// ---------------- scratch (device globals; no allocation allowed) ----------
__device__ int    g_is64;
__device__ int    g_cnt[N_NODES];
__device__ int    g_fill[N_NODES];
__device__ int    g_rowptr[N_NODES + 1];
__device__ int    g_bsum[64];
__device__ int    g_src[N_EDGES];              // CSR column = src node
__device__ float  g_dinv[N_NODES];
__device__ float  g_Af[(size_t)N_NODES * 128]; // fp32: A1, later H3
__device__ __half g_Hh[(size_t)N_NODES * 128]; // fp16: H1', later H2'
__device__ __half g_Bh[(size_t)N_NODES * 64];  // fp16: A2'

// ---------------- edge-index dtype sniffing --------------------------------
__device__ __forceinline__ int load_idx(const void* ei, long long pos) {
    if (g_is64) return (int)((const long long*)ei)[pos];
    return ((const int*)ei)[pos];
}

// ---------------- preprocessing ---------------------------------------------
__global__ void k_detect(const void* ei) {
    if (threadIdx.x == 0) {
        const unsigned long long* p = (const unsigned long long*)ei;
        int ok = 1;
        for (int k = 0; k < 16; k++)
            if (p[k] >= (unsigned long long)N_NODES) ok = 0;
        g_is64 = ok;
    }
}

__global__ void k_hist(const void* ei) {
    int e = blockIdx.x * blockDim.x + threadIdx.x;
    if (e < N_EDGES) {
        int d = load_idx(ei, (long long)N_EDGES + e);
        atomicAdd(&g_cnt[d], 1);
    }
}

__global__ void k_dinv() {
    int i = blockIdx.x * blockDim.x + threadIdx.x;
    if (i < N_NODES) g_dinv[i] = rsqrtf((float)(g_cnt[i] + 1)); // +1 self loop
}

// pass 1: block-local exclusive scan of g_cnt (1024 elems/block)
__global__ void k_scan1() {
    __shared__ int wsum[32];
    int t = threadIdx.x, lane = t & 31, wid = t >> 5;
    int i = blockIdx.x * 1024 + t;
    int c = (i < N_NODES) ? g_cnt[i] : 0;
    int v = c;
#pragma unroll
    for (int off = 1; off < 32; off <<= 1) {
        int u = __shfl_up_sync(0xffffffffu, v, off);
        if (lane >= off) v += u;
    }
    if (lane == 31) wsum[wid] = v;
    __syncthreads();
    if (wid == 0) {
        int w = wsum[lane];
#pragma unroll
        for (int off = 1; off < 32; off <<= 1) {
            int u = __shfl_up_sync(0xffffffffu, w, off);
            if (lane >= off) w += u;
        }
        wsum[lane] = w;
    }
    __syncthreads();
    int woff = (wid > 0) ? wsum[wid - 1] : 0;
    int incl = v + woff;
    if (i < N_NODES) g_rowptr[i] = incl - c;   // block-local exclusive
    if (t == 1023) g_bsum[blockIdx.x] = incl;  // block total
}

// pass 2: exclusive scan of the 49 block sums (+ total into rowptr[N])
__global__ void k_scan2() {
    __shared__ int sh[64];
    int t = threadIdx.x;
    int v = (t < SCAN_BLOCKS) ? g_bsum[t] : 0;
    sh[t] = v;
    __syncthreads();
#pragma unroll
    for (int off = 1; off < 64; off <<= 1) {
        int u = (t >= off) ? sh[t - off] : 0;
        __syncthreads();
        sh[t] += u;
        __syncthreads();
    }
    if (t < SCAN_BLOCKS) g_bsum[t] = sh[t] - v;  // exclusive
    if (t == 63) g_rowptr[N_NODES] = sh[63];     // grand total
}

// pass 3: add block offsets; init fill cursor
__global__ void k_scan3() {
    int i = blockIdx.x * 1024 + threadIdx.x;
    if (i < N_NODES) {
        int r = g_rowptr[i] + g_bsum[blockIdx.x];
        g_rowptr[i] = r;
        g_fill[i]   = r;
    }
}

__global__ void k_fill(const void* ei) {
    int e = blockIdx.x * blockDim.x + threadIdx.x;
    if (e < N_EDGES) {
        int s = load_idx(ei, e);
        int d = load_idx(ei, (long long)N_EDGES + e);
        int pos = atomicAdd(&g_fill[d], 1);
        g_src[pos] = s;
    }
}

// ---------------- wmma GEMM: Y[128 rows/CTA, NO] = X @ W -------------------
// SCALE: multiply output row r by g_dinv[r] (emits H' = dinv * XW).
template <int K, int NO, bool BIAS, bool OUTH, bool SCALE>
__global__ void __launch_bounds__(256) k_wgemm(const float* __restrict__ X,
                                               const float* __restrict__ W,
                                               const float* __restrict__ bias,
                                               void* __restrict__ Yout) {
    constexpr int AS = K + 8;
    constexpr int BS = NO + 8;
    constexpr int WCOL = NO / 2;
    constexpr int NFRAG = WCOL / 16;
    extern __shared__ __half sm[];
    __half* Ash = sm;                       // [128][AS]
    __half* Bsh = sm + 128 * AS;            // [K][BS]
    float* biasTile = (float*)(sm + 128 * AS + (size_t)K * BS); // [16][NO]

    int tid = threadIdx.x, wid = tid >> 5;
    int warp_m = wid & 3, warp_n = wid >> 2;
    int r0 = blockIdx.x * 128;

#pragma unroll 4
    for (int i = tid; i < 128 * (K / 4); i += 256) {
        int row = i / (K / 4), c4 = i % (K / 4);
        int grow = r0 + row;
        if (grow >= N_NODES) grow = 0;
        float4 v = __ldg(((const float4*)(X + (size_t)grow * K)) + c4);
        __half2* dst = (__half2*)(Ash + row * AS + c4 * 4);
        dst[0] = __floats2half2_rn(v.x, v.y);
        dst[1] = __floats2half2_rn(v.z, v.w);
    }
#pragma unroll 4
    for (int i = tid; i < K * (NO / 4); i += 256) {
        int row = i / (NO / 4), c4 = i % (NO / 4);
        float4 v = __ldg(((const float4*)(W + (size_t)row * NO)) + c4);
        __half2* dst = (__half2*)(Bsh + row * BS + c4 * 4);
        dst[0] = __floats2half2_rn(v.x, v.y);
        dst[1] = __floats2half2_rn(v.z, v.w);
    }
    if (BIAS) {
        for (int i = tid; i < 16 * NO; i += 256)
            biasTile[i] = bias[i % NO];
    }
    __syncthreads();

    wmma::fragment<wmma::accumulator, 16, 16, 16, float> acc[2][NFRAG];
#pragma unroll
    for (int i = 0; i < 2; i++)
#pragma unroll
        for (int j = 0; j < NFRAG; j++) {
            if (BIAS)
                wmma::load_matrix_sync(acc[i][j],
                                       biasTile + warp_n * WCOL + j * 16,
                                       NO, wmma::mem_row_major);
            else
                wmma::fill_fragment(acc[i][j], 0.0f);
        }

#pragma unroll
    for (int kk = 0; kk < K; kk += 16) {
        wmma::fragment<wmma::matrix_a, 16, 16, 16, __half, wmma::row_major> a0, a1;
        wmma::load_matrix_sync(a0, Ash + (warp_m * 32 + 0) * AS + kk, AS);
        wmma::load_matrix_sync(a1, Ash + (warp_m * 32 + 16) * AS + kk, AS);
#pragma unroll
        for (int j = 0; j < NFRAG; j++) {
            wmma::fragment<wmma::matrix_b, 16, 16, 16, __half, wmma::row_major> b;
            wmma::load_matrix_sync(b, Bsh + kk * BS + warp_n * WCOL + j * 16, BS);
            wmma::mma_sync(acc[0][j], a0, b, acc[0][j]);
            wmma::mma_sync(acc[1][j], a1, b, acc[1][j]);
        }
    }

    if constexpr (OUTH) {
        __syncthreads();
        float* Fsh = (float*)sm;            // [128][NO] fp32 staging
#pragma unroll
        for (int i = 0; i < 2; i++) {
            int lrow = warp_m * 32 + i * 16;
#pragma unroll
            for (int j = 0; j < NFRAG; j++)
                wmma::store_matrix_sync(Fsh + (size_t)lrow * NO + warp_n * WCOL + j * 16,
                                        acc[i][j], NO, wmma::mem_row_major);
        }
        __syncthreads();
        __half* Yh = (__half*)Yout;
#pragma unroll 4
        for (int i = tid; i < 128 * (NO / 4); i += 256) {
            int row = i / (NO / 4), c4 = i % (NO / 4);
            int grow = r0 + row;
            if (grow < N_NODES) {
                float di = SCALE ? g_dinv[grow] : 1.0f;
                float4 v = *(const float4*)(Fsh + (size_t)row * NO + c4 * 4);
                uint2 o;
                __half2 h0 = __floats2half2_rn(v.x * di, v.y * di);
                __half2 h1 = __floats2half2_rn(v.z * di, v.w * di);
                o.x = *(uint32_t*)&h0;
                o.y = *(uint32_t*)&h1;
                *(uint2*)(Yh + (size_t)grow * NO + c4 * 4) = o;
            }
        }
    } else {
        float* Y = (float*)Yout;
#pragma unroll
        for (int i = 0; i < 2; i++) {
            int grow = r0 + warp_m * 32 + i * 16;
            if (grow < N_NODES) {
#pragma unroll
                for (int j = 0; j < NFRAG; j++)
                    wmma::store_matrix_sync(Y + (size_t)grow * NO + warp_n * WCOL + j * 16,
                                            acc[i][j], NO, wmma::mem_row_major);
            }
        }
    }
}

// ---------------- sparse aggregation: one warp per node --------------------
// S = sum_e H'[src_e] (tail lanes masked) + H'[i]; val = dinv_i * S (+b, relu)
// POST: emit val * dinv_i (pre-scaled for the NEXT layer's gather).
template <int F, bool RELU, bool BIAS, bool OUTH, bool POST>
__global__ void k_agg(const __half* __restrict__ H, const float* __restrict__ b,
                      void* __restrict__ outp) {
    int gw   = (blockIdx.x * blockDim.x + threadIdx.x) >> 5;
    int lane = threadIdx.x & 31;
    if (gw >= N_NODES) return;
    int s = g_rowptr[gw], e = g_rowptr[gw + 1];

    if constexpr (F == 128) {
        float4 a0 = make_float4(0.f, 0.f, 0.f, 0.f);
        float4 a1 = make_float4(0.f, 0.f, 0.f, 0.f);
        if (e > s) {
            for (int j = s; j < e; j += 8) {
                int   sj[8];
                float wq[8];
                uint2 v[8];
#pragma unroll
                for (int q = 0; q < 8; q++) {
                    int idx = j + q;
                    sj[q] = __ldg(&g_src[idx < e ? idx : e - 1]);
                    wq[q] = (idx < e) ? 1.0f : 0.0f;
                }
#pragma unroll
                for (int q = 0; q < 8; q++)
                    v[q] = __ldg(((const uint2*)(H + (size_t)sj[q] * 128)) + lane);
#pragma unroll
                for (int q = 0; q < 8; q++) {
                    float w = wq[q];
                    float2 f0 = __half22float2(*(__half2*)&v[q].x);
                    float2 f1 = __half22float2(*(__half2*)&v[q].y);
                    float4& a = (q & 1) ? a1 : a0;
                    a.x = fmaf(w, f0.x, a.x); a.y = fmaf(w, f0.y, a.y);
                    a.z = fmaf(w, f1.x, a.z); a.w = fmaf(w, f1.y, a.w);
                }
            }
        }
        // self loop (weight 1: H' already carries dinv_i)
        uint2 vs = ((const uint2*)(H + (size_t)gw * 128))[lane];
        float2 s0 = __half22float2(*(__half2*)&vs.x);
        float2 s1 = __half22float2(*(__half2*)&vs.y);
        a0.x += s0.x; a0.y += s0.y; a0.z += s1.x; a0.w += s1.y;
        a0.x += a1.x; a0.y += a1.y; a0.z += a1.z; a0.w += a1.w;
        float di = g_dinv[gw];
        a0.x *= di; a0.y *= di; a0.z *= di; a0.w *= di;
        if (BIAS) {
            float4 bb = ((const float4*)b)[lane];
            a0.x += bb.x; a0.y += bb.y; a0.z += bb.z; a0.w += bb.w;
        }
        if (RELU) {
            a0.x = fmaxf(a0.x, 0.f); a0.y = fmaxf(a0.y, 0.f);
            a0.z = fmaxf(a0.z, 0.f); a0.w = fmaxf(a0.w, 0.f);
        }
        if (POST) { a0.x *= di; a0.y *= di; a0.z *= di; a0.w *= di; }
        if constexpr (OUTH) {
            uint2 o;
            *(__half2*)&o.x = __floats2half2_rn(a0.x, a0.y);
            *(__half2*)&o.y = __floats2half2_rn(a0.z, a0.w);
            ((uint2*)((__half*)outp + (size_t)gw * 128))[lane] = o;
        } else {
            ((float4*)((float*)outp + (size_t)gw * 128))[lane] = a0;
        }
    } else { // F == 64
        float2 a0 = make_float2(0.f, 0.f);
        float2 a1 = make_float2(0.f, 0.f);
        if (e > s) {
            for (int j = s; j < e; j += 8) {
                int      sj[8];
                float    wq[8];
                unsigned v[8];
#pragma unroll
                for (int q = 0; q < 8; q++) {
                    int idx = j + q;
                    sj[q] = __ldg(&g_src[idx < e ? idx : e - 1]);
                    wq[q] = (idx < e) ? 1.0f : 0.0f;
                }
#pragma unroll
                for (int q = 0; q < 8; q++)
                    v[q] = __ldg(((const unsigned*)(H + (size_t)sj[q] * 64)) + lane);
#pragma unroll
                for (int q = 0; q < 8; q++) {
                    float w = wq[q];
                    float2 f = __half22float2(*(__half2*)&v[q]);
                    float2& a = (q & 1) ? a1 : a0;
                    a.x = fmaf(w, f.x, a.x); a.y = fmaf(w, f.y, a.y);
                }
            }
        }
        unsigned vs = ((const unsigned*)(H + (size_t)gw * 64))[lane];
        float2 sf = __half22float2(*(__half2*)&vs);
        a0.x += sf.x; a0.y += sf.y;
        a0.x += a1.x; a0.y += a1.y;
        float di = g_dinv[gw];
        a0.x *= di; a0.y *= di;
        if (BIAS) {
            float2 bb = ((const float2*)b)[lane];
            a0.x += bb.x; a0.y += bb.y;
        }
        if (RELU) { a0.x = fmaxf(a0.x, 0.f); a0.y = fmaxf(a0.y, 0.f); }
        if (POST) { a0.x *= di; a0.y *= di; }
        if constexpr (OUTH) {
            unsigned o;
            *(__half2*)&o = __floats2half2_rn(a0.x, a0.y);
            ((unsigned*)((__half*)outp + (size_t)gw * 64))[lane] = o;
        } else {
            ((float2*)((float*)outp + (size_t)gw * 64))[lane] = a0;
        }
    }
}

// ---------------- launch ----------------------------------------------------
extern "C" void kernel_launch(void* const* d_in, const int* in_sizes, int n_in,
                              void* d_out, int out_size) {
    const float* x  = (const float*)d_in[0];
    const void*  ei = d_in[1];
    const float* W1 = (const float*)d_in[2];
    const float* b1 = (const float*)d_in[3];
    const float* W2 = (const float*)d_in[4];
    const float* b2 = (const float*)d_in[5];
    const float* W3 = (const float*)d_in[6];
    const float* b3 = (const float*)d_in[7];
    float* out = (float*)d_out;

    void *pAf = nullptr, *pHh = nullptr, *pBh = nullptr, *pCnt = nullptr;
    cudaGetSymbolAddress(&pAf, g_Af);
    cudaGetSymbolAddress(&pHh, g_Hh);
    cudaGetSymbolAddress(&pBh, g_Bh);
    cudaGetSymbolAddress(&pCnt, g_cnt);
    float*  Af = (float*)pAf;
    __half* Hh = (__half*)pHh;
    __half* Bh = (__half*)pBh;

    constexpr int SM1a = (128 * 136 + 128 * 136) * 2;
    constexpr int SM1b = 128 * 128 * 4;
    constexpr int SM1 = SM1a > SM1b ? SM1a : SM1b;                 // 69632
    constexpr int SM2a = (128 * 136 + 128 * 72) * 2;
    constexpr int SM2b = 128 * 64 * 4;
    constexpr int SM2 = SM2a > SM2b ? SM2a : SM2b;                 // 53248
    constexpr int SM3 = (128 * 72 + 64 * 136) * 2 + 16 * 128 * 4;  // 44032
    cudaFuncSetAttribute(k_wgemm<128, 128, false, true, true>,
                         cudaFuncAttributeMaxDynamicSharedMemorySize, SM1);
    cudaFuncSetAttribute(k_wgemm<128, 64, false, true, true>,
                         cudaFuncAttributeMaxDynamicSharedMemorySize, SM2);
    cudaFuncSetAttribute(k_wgemm<64, 128, true, false, false>,
                         cudaFuncAttributeMaxDynamicSharedMemorySize, SM3);

    const int TB = 256;
    int gN = (N_NODES + TB - 1) / TB;
    int gE = (N_EDGES + TB - 1) / TB;
    int aggBlocks = (N_NODES * 32 + TB - 1) / TB;
    int gT = (N_NODES + 127) / 128;

    cudaStream_t s2;
    cudaEvent_t ev0, ev1;
    cudaStreamCreateWithFlags(&s2, cudaStreamNonBlocking);
    cudaEventCreateWithFlags(&ev0, cudaEventDisableTiming);
    cudaEventCreateWithFlags(&ev1, cudaEventDisableTiming);

    // preprocessing head: detect -> cnt=0 -> hist -> dinv
    k_detect<<<1, 32>>>(ei);
    cudaMemsetAsync(pCnt, 0, N_NODES * sizeof(int), 0);
    k_hist<<<gE, TB>>>(ei);
    k_dinv<<<gN, TB>>>();

    // fork: wgemm1 needs only x, W1, dinv -> runs concurrent with scan+fill
    cudaEventRecord(ev0, 0);
    cudaStreamWaitEvent(s2, ev0, 0);
    k_wgemm<128, 128, false, true, true><<<gT, 256, SM1, s2>>>(x, W1, nullptr, Hh);
    cudaEventRecord(ev1, s2);

    // CSR build on the main stream
    k_scan1<<<SCAN_BLOCKS, 1024>>>();
    k_scan2<<<1, 64>>>();
    k_scan3<<<SCAN_BLOCKS, 1024>>>();
    k_fill<<<gE, TB>>>(ei);

    cudaStreamWaitEvent(0, ev1, 0);   // join: agg1 needs H1' + CSR

    // layer 1: A1 = relu(dinv*(S(H1')) + b1)                 [fp32]
    k_agg<128, true, true, false, false><<<aggBlocks, TB>>>(Hh, b1, Af);
    // layer 2: H2' = dinv*(A1@W2) [fp16]; A2' = dinv*relu(dinv*S(H2')+b2) [fp16]
    k_wgemm<128, 64, false, true, true><<<gT, 256, SM2>>>(Af, W2, nullptr, Hh);
    k_agg<64, true, true, true, true><<<aggBlocks, TB>>>(Hh, b2, Bh);
    // layer 3: H3 = dinv*S(A2') [fp32]; out = H3@W3 + b3
    k_agg<64, false, false, false, false><<<aggBlocks, TB>>>(Bh, nullptr, Af);
    k_wgemm<64, 128, true, false, false><<<gT, 256, SM3>>>(Af, W3, b3, out);
}

// round 14
// speedup vs baseline: 1.2789x; 1.0296x over previous
#include <cuda_runtime.h>
#include <cuda_fp16.h>
#include <mma.h>
#include <cstdint>

using namespace nvcuda;

#define N_NODES 50000
#define N_EDGES 800000
#define SCAN_BLOCKS 49

// ---------------- scratch (device globals; no allocation allowed) ----------
__device__ int    g_is64;
__device__ int    g_cnt[N_NODES];
__device__ int    g_fill[N_NODES];
__device__ int    g_rowptr[N_NODES + 1];
__device__ int    g_bsum[64];
__device__ int    g_src[N_EDGES];              // CSR column = src node
__device__ float  g_dinv[N_NODES];
__device__ __half g_Hh[(size_t)N_NODES * 128]; // H1', later H2'
__device__ __half g_Ch[(size_t)N_NODES * 128]; // A1 (fp16), later H3 (fp16)
__device__ __half g_Bh[(size_t)N_NODES * 64];  // A2'

// ---------------- edge-index dtype sniffing --------------------------------
__device__ __forceinline__ int load_idx(const void* ei, long long pos) {
    if (g_is64) return (int)((const long long*)ei)[pos];
    return ((const int*)ei)[pos];
}

// ---------------- preprocessing ---------------------------------------------
__global__ void k_detect(const void* ei) {
    if (threadIdx.x == 0) {
        const unsigned long long* p = (const unsigned long long*)ei;
        int ok = 1;
        for (int k = 0; k < 16; k++)
            if (p[k] >= (unsigned long long)N_NODES) ok = 0;
        g_is64 = ok;
    }
}

__global__ void k_hist(const void* ei) {
    int e = blockIdx.x * blockDim.x + threadIdx.x;
    if (e < N_EDGES) {
        int d = load_idx(ei, (long long)N_EDGES + e);
        atomicAdd(&g_cnt[d], 1);
    }
}

__global__ void k_dinv() {
    int i = blockIdx.x * blockDim.x + threadIdx.x;
    if (i < N_NODES) g_dinv[i] = rsqrtf((float)(g_cnt[i] + 1)); // +1 self loop
}

// pass 1: block-local exclusive scan of g_cnt (1024 elems/block)
__global__ void k_scan1() {
    __shared__ int wsum[32];
    int t = threadIdx.x, lane = t & 31, wid = t >> 5;
    int i = blockIdx.x * 1024 + t;
    int c = (i < N_NODES) ? g_cnt[i] : 0;
    int v = c;
#pragma unroll
    for (int off = 1; off < 32; off <<= 1) {
        int u = __shfl_up_sync(0xffffffffu, v, off);
        if (lane >= off) v += u;
    }
    if (lane == 31) wsum[wid] = v;
    __syncthreads();
    if (wid == 0) {
        int w = wsum[lane];
#pragma unroll
        for (int off = 1; off < 32; off <<= 1) {
            int u = __shfl_up_sync(0xffffffffu, w, off);
            if (lane >= off) w += u;
        }
        wsum[lane] = w;
    }
    __syncthreads();
    int woff = (wid > 0) ? wsum[wid - 1] : 0;
    int incl = v + woff;
    if (i < N_NODES) g_rowptr[i] = incl - c;   // block-local exclusive
    if (t == 1023) g_bsum[blockIdx.x] = incl;  // block total
}

// pass 2 (merged): every block re-derives the bsum prefix locally, then adds
// its offset and initializes the fill cursor. Block 0 writes rowptr[N].
__global__ void k_scan3() {
    __shared__ int sh[SCAN_BLOCKS];
    __shared__ int s_total;
    int t = threadIdx.x;
    if (t < SCAN_BLOCKS) sh[t] = g_bsum[t];
    __syncthreads();
    if (t == 0) {
        int run = 0;
#pragma unroll
        for (int k = 0; k < SCAN_BLOCKS; k++) {
            int c = sh[k];
            sh[k] = run;
            run += c;
        }
        s_total = run;
    }
    __syncthreads();
    int off = sh[blockIdx.x];
    int i = blockIdx.x * 1024 + t;
    if (i < N_NODES) {
        int r = g_rowptr[i] + off;
        g_rowptr[i] = r;
        g_fill[i]   = r;
    }
    if (blockIdx.x == 0 && t == 0) g_rowptr[N_NODES] = s_total;
}

__global__ void k_fill(const void* ei) {
    int e = blockIdx.x * blockDim.x + threadIdx.x;
    if (e < N_EDGES) {
        int s = load_idx(ei, e);
        int d = load_idx(ei, (long long)N_EDGES + e);
        int pos = atomicAdd(&g_fill[d], 1);
        g_src[pos] = s;
    }
}

// ---------------- wmma GEMM: Y[128 rows/CTA, NO] = X @ W -------------------
// INH: X is fp16 (copy rows); else fp32 (convert). SCALE: row *= dinv.
// OUTH: fp16 output via smem staging.
template <int K, int NO, bool BIAS, bool OUTH, bool SCALE, bool INH>
__global__ void __launch_bounds__(256) k_wgemm(const void* __restrict__ Xin,
                                               const float* __restrict__ W,
                                               const float* __restrict__ bias,
                                               void* __restrict__ Yout) {
    constexpr int AS = K + 8;
    constexpr int BS = NO + 8;
    constexpr int WCOL = NO / 2;
    constexpr int NFRAG = WCOL / 16;
    extern __shared__ __half sm[];
    __half* Ash = sm;                       // [128][AS]
    __half* Bsh = sm + 128 * AS;            // [K][BS]
    float* biasTile = (float*)(sm + 128 * AS + (size_t)K * BS); // [16][NO]

    int tid = threadIdx.x, wid = tid >> 5;
    int warp_m = wid & 3, warp_n = wid >> 2;
    int r0 = blockIdx.x * 128;

    // stage A (chunks of 4 values)
#pragma unroll 4
    for (int i = tid; i < 128 * (K / 4); i += 256) {
        int row = i / (K / 4), c4 = i % (K / 4);
        int grow = r0 + row;
        if (grow >= N_NODES) grow = 0;
        if constexpr (INH) {
            uint2 v = __ldg(((const uint2*)((const __half*)Xin + (size_t)grow * K)) + c4);
            *(uint2*)(Ash + row * AS + c4 * 4) = v;
        } else {
            float4 v = __ldg(((const float4*)((const float*)Xin + (size_t)grow * K)) + c4);
            __half2* dst = (__half2*)(Ash + row * AS + c4 * 4);
            dst[0] = __floats2half2_rn(v.x, v.y);
            dst[1] = __floats2half2_rn(v.z, v.w);
        }
    }
#pragma unroll 4
    for (int i = tid; i < K * (NO / 4); i += 256) {
        int row = i / (NO / 4), c4 = i % (NO / 4);
        float4 v = __ldg(((const float4*)(W + (size_t)row * NO)) + c4);
        __half2* dst = (__half2*)(Bsh + row * BS + c4 * 4);
        dst[0] = __floats2half2_rn(v.x, v.y);
        dst[1] = __floats2half2_rn(v.z, v.w);
    }
    if (BIAS) {
        for (int i = tid; i < 16 * NO; i += 256)
            biasTile[i] = bias[i % NO];
    }
    __syncthreads();

    wmma::fragment<wmma::accumulator, 16, 16, 16, float> acc[2][NFRAG];
#pragma unroll
    for (int i = 0; i < 2; i++)
#pragma unroll
        for (int j = 0; j < NFRAG; j++) {
            if (BIAS)
                wmma::load_matrix_sync(acc[i][j],
                                       biasTile + warp_n * WCOL + j * 16,
                                       NO, wmma::mem_row_major);
            else
                wmma::fill_fragment(acc[i][j], 0.0f);
        }

#pragma unroll
    for (int kk = 0; kk < K; kk += 16) {
        wmma::fragment<wmma::matrix_a, 16, 16, 16, __half, wmma::row_major> a0, a1;
        wmma::load_matrix_sync(a0, Ash + (warp_m * 32 + 0) * AS + kk, AS);
        wmma::load_matrix_sync(a1, Ash + (warp_m * 32 + 16) * AS + kk, AS);
#pragma unroll
        for (int j = 0; j < NFRAG; j++) {
            wmma::fragment<wmma::matrix_b, 16, 16, 16, __half, wmma::row_major> b;
            wmma::load_matrix_sync(b, Bsh + kk * BS + warp_n * WCOL + j * 16, BS);
            wmma::mma_sync(acc[0][j], a0, b, acc[0][j]);
            wmma::mma_sync(acc[1][j], a1, b, acc[1][j]);
        }
    }

    if constexpr (OUTH) {
        __syncthreads();
        float* Fsh = (float*)sm;            // [128][NO] fp32 staging
#pragma unroll
        for (int i = 0; i < 2; i++) {
            int lrow = warp_m * 32 + i * 16;
#pragma unroll
            for (int j = 0; j < NFRAG; j++)
                wmma::store_matrix_sync(Fsh + (size_t)lrow * NO + warp_n * WCOL + j * 16,
                                        acc[i][j], NO, wmma::mem_row_major);
        }
        __syncthreads();
        __half* Yh = (__half*)Yout;
#pragma unroll 4
        for (int i = tid; i < 128 * (NO / 4); i += 256) {
            int row = i / (NO / 4), c4 = i % (NO / 4);
            int grow = r0 + row;
            if (grow < N_NODES) {
                float di = SCALE ? g_dinv[grow] : 1.0f;
                float4 v = *(const float4*)(Fsh + (size_t)row * NO + c4 * 4);
                uint2 o;
                __half2 h0 = __floats2half2_rn(v.x * di, v.y * di);
                __half2 h1 = __floats2half2_rn(v.z * di, v.w * di);
                o.x = *(uint32_t*)&h0;
                o.y = *(uint32_t*)&h1;
                *(uint2*)(Yh + (size_t)grow * NO + c4 * 4) = o;
            }
        }
    } else {
        float* Y = (float*)Yout;
#pragma unroll
        for (int i = 0; i < 2; i++) {
            int grow = r0 + warp_m * 32 + i * 16;
            if (grow < N_NODES) {
#pragma unroll
                for (int j = 0; j < NFRAG; j++)
                    wmma::store_matrix_sync(Y + (size_t)grow * NO + warp_n * WCOL + j * 16,
                                            acc[i][j], NO, wmma::mem_row_major);
            }
        }
    }
}

// ---------------- sparse aggregation: one warp per node --------------------
// S = sum_e H'[src_e] (tail masked) + H'[i]; val = dinv_i * S (+b, relu)
// POST: emit val * dinv_i (pre-scaled for next layer's gather).
template <int F, bool RELU, bool BIAS, bool OUTH, bool POST>
__global__ void k_agg(const __half* __restrict__ H, const float* __restrict__ b,
                      void* __restrict__ outp) {
    int gw   = (blockIdx.x * blockDim.x + threadIdx.x) >> 5;
    int lane = threadIdx.x & 31;
    if (gw >= N_NODES) return;
    int s = g_rowptr[gw], e = g_rowptr[gw + 1];

    if constexpr (F == 128) {
        float4 a0 = make_float4(0.f, 0.f, 0.f, 0.f);
        float4 a1 = make_float4(0.f, 0.f, 0.f, 0.f);
        if (e > s) {
            for (int j = s; j < e; j += 8) {
                int   sj[8];
                float wq[8];
                uint2 v[8];
#pragma unroll
                for (int q = 0; q < 8; q++) {
                    int idx = j + q;
                    sj[q] = __ldg(&g_src[idx < e ? idx : e - 1]);
                    wq[q] = (idx < e) ? 1.0f : 0.0f;
                }
#pragma unroll
                for (int q = 0; q < 8; q++)
                    v[q] = __ldg(((const uint2*)(H + (size_t)sj[q] * 128)) + lane);
#pragma unroll
                for (int q = 0; q < 8; q++) {
                    float w = wq[q];
                    float2 f0 = __half22float2(*(__half2*)&v[q].x);
                    float2 f1 = __half22float2(*(__half2*)&v[q].y);
                    float4& a = (q & 1) ? a1 : a0;
                    a.x = fmaf(w, f0.x, a.x); a.y = fmaf(w, f0.y, a.y);
                    a.z = fmaf(w, f1.x, a.z); a.w = fmaf(w, f1.y, a.w);
                }
            }
        }
        uint2 vs = ((const uint2*)(H + (size_t)gw * 128))[lane];
        float2 s0 = __half22float2(*(__half2*)&vs.x);
        float2 s1 = __half22float2(*(__half2*)&vs.y);
        a0.x += s0.x; a0.y += s0.y; a0.z += s1.x; a0.w += s1.y;
        a0.x += a1.x; a0.y += a1.y; a0.z += a1.z; a0.w += a1.w;
        float di = g_dinv[gw];
        a0.x *= di; a0.y *= di; a0.z *= di; a0.w *= di;
        if (BIAS) {
            float4 bb = ((const float4*)b)[lane];
            a0.x += bb.x; a0.y += bb.y; a0.z += bb.z; a0.w += bb.w;
        }
        if (RELU) {
            a0.x = fmaxf(a0.x, 0.f); a0.y = fmaxf(a0.y, 0.f);
            a0.z = fmaxf(a0.z, 0.f); a0.w = fmaxf(a0.w, 0.f);
        }
        if (POST) { a0.x *= di; a0.y *= di; a0.z *= di; a0.w *= di; }
        if constexpr (OUTH) {
            uint2 o;
            *(__half2*)&o.x = __floats2half2_rn(a0.x, a0.y);
            *(__half2*)&o.y = __floats2half2_rn(a0.z, a0.w);
            ((uint2*)((__half*)outp + (size_t)gw * 128))[lane] = o;
        } else {
            ((float4*)((float*)outp + (size_t)gw * 128))[lane] = a0;
        }
    } else { // F == 64
        float2 a0 = make_float2(0.f, 0.f);
        float2 a1 = make_float2(0.f, 0.f);
        if (e > s) {
            for (int j = s; j < e; j += 8) {
                int      sj[8];
                float    wq[8];
                unsigned v[8];
#pragma unroll
                for (int q = 0; q < 8; q++) {
                    int idx = j + q;
                    sj[q] = __ldg(&g_src[idx < e ? idx : e - 1]);
                    wq[q] = (idx < e) ? 1.0f : 0.0f;
                }
#pragma unroll
                for (int q = 0; q < 8; q++)
                    v[q] = __ldg(((const unsigned*)(H + (size_t)sj[q] * 64)) + lane);
#pragma unroll
                for (int q = 0; q < 8; q++) {
                    float w = wq[q];
                    float2 f = __half22float2(*(__half2*)&v[q]);
                    float2& a = (q & 1) ? a1 : a0;
                    a.x = fmaf(w, f.x, a.x); a.y = fmaf(w, f.y, a.y);
                }
            }
        }
        unsigned vs = ((const unsigned*)(H + (size_t)gw * 64))[lane];
        float2 sf = __half22float2(*(__half2*)&vs);
        a0.x += sf.x; a0.y += sf.y;
        a0.x += a1.x; a0.y += a1.y;
        float di = g_dinv[gw];
        a0.x *= di; a0.y *= di;
        if (BIAS) {
            float2 bb = ((const float2*)b)[lane];
            a0.x += bb.x; a0.y += bb.y;
        }
        if (RELU) { a0.x = fmaxf(a0.x, 0.f); a0.y = fmaxf(a0.y, 0.f); }
        if (POST) { a0.x *= di; a0.y *= di; }
        if constexpr (OUTH) {
            unsigned o;
            *(__half2*)&o = __floats2half2_rn(a0.x, a0.y);
            ((unsigned*)((__half*)outp + (size_t)gw * 64))[lane] = o;
        } else {
            ((float2*)((float*)outp + (size_t)gw * 64))[lane] = a0;
        }
    }
}

// ---------------- launch ----------------------------------------------------
extern "C" void kernel_launch(void* const* d_in, const int* in_sizes, int n_in,
                              void* d_out, int out_size) {
    const float* x  = (const float*)d_in[0];
    const void*  ei = d_in[1];
    const float* W1 = (const float*)d_in[2];
    const float* b1 = (const float*)d_in[3];
    const float* W2 = (const float*)d_in[4];
    const float* b2 = (const float*)d_in[5];
    const float* W3 = (const float*)d_in[6];
    const float* b3 = (const float*)d_in[7];
    float* out = (float*)d_out;

    void *pHh = nullptr, *pCh = nullptr, *pBh = nullptr, *pCnt = nullptr;
    cudaGetSymbolAddress(&pHh, g_Hh);
    cudaGetSymbolAddress(&pCh, g_Ch);
    cudaGetSymbolAddress(&pBh, g_Bh);
    cudaGetSymbolAddress(&pCnt, g_cnt);
    __half* Hh = (__half*)pHh;
    __half* Ch = (__half*)pCh;
    __half* Bh = (__half*)pBh;

    constexpr int SM1a = (128 * 136 + 128 * 136) * 2;
    constexpr int SM1b = 128 * 128 * 4;
    constexpr int SM1 = SM1a > SM1b ? SM1a : SM1b;                 // 69632
    constexpr int SM2a = (128 * 136 + 128 * 72) * 2;
    constexpr int SM2b = 128 * 64 * 4;
    constexpr int SM2 = SM2a > SM2b ? SM2a : SM2b;                 // 53248
    constexpr int SM3 = (128 * 72 + 64 * 136) * 2 + 16 * 128 * 4;  // 44032
    cudaFuncSetAttribute(k_wgemm<128, 128, false, true, true, false>,
                         cudaFuncAttributeMaxDynamicSharedMemorySize, SM1);
    cudaFuncSetAttribute(k_wgemm<128, 64, false, true, true, true>,
                         cudaFuncAttributeMaxDynamicSharedMemorySize, SM2);
    cudaFuncSetAttribute(k_wgemm<64, 128, true, false, false, true>,
                         cudaFuncAttributeMaxDynamicSharedMemorySize, SM3);

    const int TB = 256;
    int gN = (N_NODES + TB - 1) / TB;
    int gE = (N_EDGES + TB - 1) / TB;
    int aggBlocks = (N_NODES * 32 + TB - 1) / TB;
    int gT = (N_NODES + 127) / 128;

    cudaStream_t s2;
    cudaEvent_t ev0, ev1;
    cudaStreamCreateWithFlags(&s2, cudaStreamNonBlocking);
    cudaEventCreateWithFlags(&ev0, cudaEventDisableTiming);
    cudaEventCreateWithFlags(&ev1, cudaEventDisableTiming);

    // preprocessing head: detect -> cnt=0 -> hist -> dinv
    k_detect<<<1, 32>>>(ei);
    cudaMemsetAsync(pCnt, 0, N_NODES * sizeof(int), 0);
    k_hist<<<gE, TB>>>(ei);
    k_dinv<<<gN, TB>>>();

    // fork: wgemm1 needs only x, W1, dinv -> concurrent with scan+fill
    cudaEventRecord(ev0, 0);
    cudaStreamWaitEvent(s2, ev0, 0);
    k_wgemm<128, 128, false, true, true, false><<<gT, 256, SM1, s2>>>(x, W1, nullptr, Hh);
    cudaEventRecord(ev1, s2);

    // CSR build on the main stream
    k_scan1<<<SCAN_BLOCKS, 1024>>>();
    k_scan3<<<SCAN_BLOCKS, 1024>>>();
    k_fill<<<gE, TB>>>(ei);

    cudaStreamWaitEvent(0, ev1, 0);   // join: agg1 needs H1' + CSR

    // layer 1: A1 = relu(dinv*S(H1') + b1)                   [fp16 -> Ch]
    k_agg<128, true, true, true, false><<<aggBlocks, TB>>>(Hh, b1, Ch);
    // layer 2: H2' = dinv*(A1@W2) [fp16]; A2' = dinv*relu(dinv*S(H2')+b2) [fp16]
    k_wgemm<128, 64, false, true, true, true><<<gT, 256, SM2>>>(Ch, W2, nullptr, Hh);
    k_agg<64, true, true, true, true><<<aggBlocks, TB>>>(Hh, b2, Bh);
    // layer 3: H3 = dinv*S(A2') [fp16 -> Ch]; out = H3@W3 + b3
    k_agg<64, false, false, true, false><<<aggBlocks, TB>>>(Bh, nullptr, Ch);
    k_wgemm<64, 128, true, false, false, true><<<gT, 256, SM3>>>(Ch, W3, b3, out);
}